// round 4
// baseline (speedup 1.0000x reference)
#include <cuda_runtime.h>
#include <cuda_fp16.h>
#include <cuda_bf16.h>

// TokenAwareEmbedding: per-token NF4 dequant + special-token override.
//   0: input_ids          int32|int64 [8, 2048]
//   1: main_quantized     int32       [804112, 64]
//   2: main_scales        fp32        [804112]
//   3: special_embeddings fp32|fp16|bf16 [256, 1024]
//   4: special_indices    int32|int64 [256] (sorted)
// output: fp32 [8, 2048, 1024]

#define VOCAB 50257
#define DIM 1024
#define NTOK (8 * 2048)
#define NSPEC 256
#define NSPEC_ELEMS (NSPEC * DIM)

__constant__ float c_nf4[16] = {
    -1.0f, -0.6962f, -0.5251f, -0.3949f, -0.2844f, -0.1848f, -0.0911f, 0.0f,
    0.0796f, 0.1609f, 0.2461f, 0.3379f, 0.4407f, 0.5626f, 0.723f, 1.0f};

// g_flags[0] = index width (1 = int64, 0 = int32)
// g_flags[1] = spec dtype  (0 = fp32, 1 = fp16, 2 = bf16)
__device__ int   g_flags[2];
__device__ float g_spec_f32[NSPEC_ELEMS];  // 1 MB fp32 scratch
__device__ int   g_map[VOCAB];             // vocab -> special row (-1 = none)
__device__ int   g_rec[NTOK];              // packed: t | (row+1)<<20

__device__ __forceinline__ float finite_abs(float v) {
    return isfinite(v) ? fabsf(v) : 1e30f;
}

__device__ __forceinline__ long long load_idx(const void* p, int i, bool wide) {
    if (wide) return ((const long long*)p)[i];
    return (long long)((const int*)p)[i];
}

// ── K1: dtype detection (1 block) ───────────────────────────────────────────
__global__ void detect_kernel(const int* __restrict__ ids32,
                              const unsigned short* __restrict__ specu) {
    __shared__ float s_sum[3][8];
    __shared__ float s_max[3][8];
    const int tid = threadIdx.x;
    float sum[3] = {0.f, 0.f, 0.f};
    float mx[3] = {0.f, 0.f, 0.f};
    #pragma unroll
    for (int k = 0; k < 4; k++) {
        int i = tid * 4 + k;  // first 1024 elements
        float vh = finite_abs(__half2float(((const __half*)specu)[i]));
        float vb = finite_abs(__bfloat162float(((const __nv_bfloat16*)specu)[i]));
        float vf = finite_abs(((const float*)specu)[i]);
        sum[0] += vh; mx[0] = fmaxf(mx[0], vh);
        sum[1] += vb; mx[1] = fmaxf(mx[1], vb);
        sum[2] += vf; mx[2] = fmaxf(mx[2], vf);
    }
    #pragma unroll
    for (int c = 0; c < 3; c++) {
        #pragma unroll
        for (int o = 16; o > 0; o >>= 1) {
            sum[c] += __shfl_down_sync(0xFFFFFFFFu, sum[c], o);
            mx[c] = fmaxf(mx[c], __shfl_down_sync(0xFFFFFFFFu, mx[c], o));
        }
        if ((tid & 31) == 0) { s_sum[c][tid >> 5] = sum[c]; s_max[c][tid >> 5] = mx[c]; }
    }
    __syncthreads();
    if (tid == 0) {
        float S[3], M[3];
        #pragma unroll
        for (int c = 0; c < 3; c++) {
            S[c] = 0.f; M[c] = 0.f;
            #pragma unroll
            for (int w = 0; w < 8; w++) { S[c] += s_sum[c][w]; M[c] = fmaxf(M[c], s_max[c][w]); }
            S[c] *= (1.0f / 1024.0f);  // mean |x|; N(0,1) -> ~0.798
        }
        int dt;
        if (M[0] < 10.f && fabsf(S[0] - 0.8f) < 0.3f)      dt = 1;  // fp16
        else if (M[1] < 10.f && fabsf(S[1] - 0.8f) < 0.3f) dt = 2;  // bf16
        else                                                dt = 0;  // fp32
        g_flags[1] = dt;

        bool wide = true;
        #pragma unroll
        for (int k = 1; k < 64; k += 2) wide &= (ids32[k] == 0);
        g_flags[0] = wide ? 1 : 0;
    }
}

// ── K2: init map + convert special embeddings to fp32 ───────────────────────
__global__ __launch_bounds__(256)
void prep_convert_kernel(const unsigned short* __restrict__ specu) {
    const int gid = blockIdx.x * 256 + threadIdx.x;
    if (gid < VOCAB) g_map[gid] = -1;
    if (gid < NSPEC_ELEMS) {
        const int dt = g_flags[1];
        float v;
        if (dt == 0)      v = ((const float*)specu)[gid];
        else if (dt == 1) v = __half2float(((const __half*)specu)[gid]);
        else              v = __bfloat162float(((const __nv_bfloat16*)specu)[gid]);
        g_spec_f32[gid] = v;
    }
}

// ── K3: scatter special rows (last-wins via atomicMax on sorted indices) ────
__global__ void prep_scatter_kernel(const void* __restrict__ sidx) {
    const bool wide = (g_flags[0] != 0);
    const int i = threadIdx.x;
    long long t = load_idx(sidx, i, wide);
    if (t >= 0 && t < VOCAB) atomicMax(&g_map[(int)t], i);
}

// ── K4: normalize token ids + resolve special row -> packed record ──────────
__global__ __launch_bounds__(256)
void prep_rec_kernel(const void* __restrict__ ids) {
    const int tok = blockIdx.x * 256 + threadIdx.x;
    if (tok >= NTOK) return;
    const bool wide = (g_flags[0] != 0);
    long long t = load_idx(ids, tok, wide);
    if (t < 0) t = 0;
    if (t >= VOCAB) t = VOCAB - 1;
    const int r = g_map[(int)t];
    g_rec[tok] = (int)t | ((r + 1) << 20);
}

// ── K5: main gather/dequant ─────────────────────────────────────────────────
__global__ __launch_bounds__(256)
void tok_embed_kernel(const int* __restrict__ quant,
                      const float* __restrict__ scales,
                      float* __restrict__ out) {
    const int tok = blockIdx.x;
    const int pack = __ldg(g_rec + tok);      // L2 broadcast, 1 hop
    const int t = pack & 0xFFFFF;
    const int r = (pack >> 20) - 1;
    const int d = threadIdx.x * 4;

    float4 o;
    if (r >= 0) {
        o = *reinterpret_cast<const float4*>(g_spec_f32 + (size_t)r * DIM + d);
    } else {
        const int4 qi = *reinterpret_cast<const int4*>(quant + (size_t)t * DIM + d);
        const float s = __ldg(scales + (size_t)t * (DIM / 64) + (d >> 6));
        o = make_float4(c_nf4[qi.x & 15] * s, c_nf4[qi.y & 15] * s,
                        c_nf4[qi.z & 15] * s, c_nf4[qi.w & 15] * s);
    }
    // Streaming store: output is never re-read; keep L2 for quant-row reuse.
    __stcs(reinterpret_cast<float4*>(out + (size_t)tok * DIM + d), o);
}

extern "C" void kernel_launch(void* const* d_in, const int* in_sizes, int n_in,
                              void* d_out, int out_size) {
    const void*  ids    = d_in[0];
    const int*   quant  = (const int*)d_in[1];
    const float* scales = (const float*)d_in[2];
    const unsigned short* spec = (const unsigned short*)d_in[3];
    const void*  sidx   = d_in[4];
    float* out = (float*)d_out;

    detect_kernel<<<1, 256>>>((const int*)ids, spec);
    prep_convert_kernel<<<(NSPEC_ELEMS + 255) / 256, 256>>>(spec);
    prep_scatter_kernel<<<1, NSPEC>>>(sidx);
    prep_rec_kernel<<<(NTOK + 255) / 256, 256>>>(ids);
    tok_embed_kernel<<<NTOK, 256>>>(quant, scales, out);
}

// round 5
// speedup vs baseline: 1.1875x; 1.1875x over previous
#include <cuda_runtime.h>
#include <cuda_fp16.h>
#include <cuda_bf16.h>

// TokenAwareEmbedding: per-token NF4 dequant + special-token override.
//   0: input_ids          int32|int64 [8, 2048]
//   1: main_quantized     int32       [804112, 64]
//   2: main_scales        fp32        [804112]
//   3: special_embeddings fp32|fp16|bf16 [256, 1024]
//   4: special_indices    int32|int64 [256] (sorted)
// output: fp32 [8, 2048, 1024]

#define VOCAB 50257
#define DIM 1024
#define NTOK (8 * 2048)
#define NSPEC 256
#define TPB 4            // tokens per block in main kernel

__constant__ float c_nf4[16] = {
    -1.0f, -0.6962f, -0.5251f, -0.3949f, -0.2844f, -0.1848f, -0.0911f, 0.0f,
    0.0796f, 0.1609f, 0.2461f, 0.3379f, 0.4407f, 0.5626f, 0.723f, 1.0f};

// g_flags[0] = index width (1 = int64, 0 = int32)
// g_flags[1] = spec dtype  (0 = fp32, 1 = fp16, 2 = bf16)
__device__ int g_flags[2];
// packed per-token record: t[0:16) | (row+1)[16:25) | dt[25:27)
__device__ int g_rec[NTOK];

__device__ __forceinline__ float finite_abs(float v) {
    return isfinite(v) ? fabsf(v) : 1e30f;
}

__device__ __forceinline__ long long load_idx(const void* p, int i, bool wide) {
    if (wide) return ((const long long*)p)[i];
    return (long long)((const int*)p)[i];
}

// ── K1: dtype/width detection (1 block) ─────────────────────────────────────
__global__ void detect_kernel(const int* __restrict__ ids32,
                              const unsigned short* __restrict__ specu) {
    __shared__ float s_sum[3][8];
    __shared__ float s_max[3][8];
    const int tid = threadIdx.x;
    float sum[3] = {0.f, 0.f, 0.f};
    float mx[3] = {0.f, 0.f, 0.f};
    #pragma unroll
    for (int k = 0; k < 4; k++) {
        int i = tid * 4 + k;  // first 1024 elements
        float vh = finite_abs(__half2float(((const __half*)specu)[i]));
        float vb = finite_abs(__bfloat162float(((const __nv_bfloat16*)specu)[i]));
        float vf = finite_abs(((const float*)specu)[i]);
        sum[0] += vh; mx[0] = fmaxf(mx[0], vh);
        sum[1] += vb; mx[1] = fmaxf(mx[1], vb);
        sum[2] += vf; mx[2] = fmaxf(mx[2], vf);
    }
    #pragma unroll
    for (int c = 0; c < 3; c++) {
        #pragma unroll
        for (int o = 16; o > 0; o >>= 1) {
            sum[c] += __shfl_down_sync(0xFFFFFFFFu, sum[c], o);
            mx[c] = fmaxf(mx[c], __shfl_down_sync(0xFFFFFFFFu, mx[c], o));
        }
        if ((tid & 31) == 0) { s_sum[c][tid >> 5] = sum[c]; s_max[c][tid >> 5] = mx[c]; }
    }
    __syncthreads();
    if (tid == 0) {
        float S[3], M[3];
        #pragma unroll
        for (int c = 0; c < 3; c++) {
            S[c] = 0.f; M[c] = 0.f;
            #pragma unroll
            for (int w = 0; w < 8; w++) { S[c] += s_sum[c][w]; M[c] = fmaxf(M[c], s_max[c][w]); }
            S[c] *= (1.0f / 1024.0f);  // mean |x|; N(0,1) -> ~0.798
        }
        int dt;
        if (M[0] < 10.f && fabsf(S[0] - 0.8f) < 0.3f)      dt = 1;  // fp16
        else if (M[1] < 10.f && fabsf(S[1] - 0.8f) < 0.3f) dt = 2;  // bf16
        else                                                dt = 0;  // fp32
        g_flags[1] = dt;

        // index width: int64 values < 2^31 have zero odd int32 words
        bool wide = true;
        #pragma unroll
        for (int k = 1; k < 64; k += 2) wide &= (ids32[k] == 0);
        g_flags[0] = wide ? 1 : 0;
    }
}

// ── K2: per-token record (binary search over shared sidx) ───────────────────
__global__ __launch_bounds__(256)
void prep_rec_kernel(const void* __restrict__ ids,
                     const void* __restrict__ sidx) {
    __shared__ int s_sidx[NSPEC];
    const bool wide = (g_flags[0] != 0);
    const int dt = g_flags[1];
    s_sidx[threadIdx.x] = (int)load_idx(sidx, threadIdx.x, wide);
    __syncthreads();

    const int tok = blockIdx.x * 256 + threadIdx.x;
    long long tl = load_idx(ids, tok, wide);
    if (tl < 0) tl = 0;
    if (tl >= VOCAB) tl = VOCAB - 1;
    const int t = (int)tl;

    // upper_bound; last-wins for duplicate sorted indices (XLA scatter)
    int lo = 0, hi = NSPEC;
    #pragma unroll
    for (int it = 0; it < 8; it++) {
        int mid = (lo + hi) >> 1;
        if (s_sidx[mid] <= t) lo = mid + 1; else hi = mid;
    }
    const int r = (lo > 0 && s_sidx[lo - 1] == t) ? (lo - 1) : -1;
    g_rec[tok] = t | ((r + 1) << 16) | (dt << 25);
}

// ── K3: main gather/dequant, 4 tokens per block (front-batched loads) ───────
__global__ __launch_bounds__(256)
void tok_embed_kernel(const int* __restrict__ quant,
                      const float* __restrict__ scales,
                      const unsigned short* __restrict__ specu,
                      float* __restrict__ out) {
    const int tok0 = blockIdx.x * TPB;
    const int4 rr = *reinterpret_cast<const int4*>(g_rec + tok0);  // broadcast
    const int rec[TPB] = {rr.x, rr.y, rr.z, rr.w};
    const int d = threadIdx.x * 4;  // 4 consecutive dims per thread

    // Phase 1: issue all independent loads
    int4 q[TPB];
    float sc[TPB];
    #pragma unroll
    for (int j = 0; j < TPB; j++) {
        const int t = rec[j] & 0xFFFF;
        const int r = ((rec[j] >> 16) & 0x1FF) - 1;
        if (r < 0) {
            q[j] = *reinterpret_cast<const int4*>(quant + (size_t)t * DIM + d);
            sc[j] = __ldg(scales + t * (DIM / 64) + (d >> 6));
        }
    }

    // Phase 2: compute + store
    #pragma unroll
    for (int j = 0; j < TPB; j++) {
        const int r = ((rec[j] >> 16) & 0x1FF) - 1;
        float4 o;
        if (r >= 0) {
            const int dt = (rec[j] >> 25) & 3;
            const size_t base = (size_t)r * DIM + d;
            if (dt == 0) {
                o = *reinterpret_cast<const float4*>((const float*)specu + base);
            } else if (dt == 1) {
                const __half2* sp = reinterpret_cast<const __half2*>((const __half*)specu + base);
                float2 fa = __half22float2(sp[0]);
                float2 fb = __half22float2(sp[1]);
                o = make_float4(fa.x, fa.y, fb.x, fb.y);
            } else {
                const __nv_bfloat162* sp =
                    reinterpret_cast<const __nv_bfloat162*>((const __nv_bfloat16*)specu + base);
                float2 fa = __bfloat1622float2(sp[0]);
                float2 fb = __bfloat1622float2(sp[1]);
                o = make_float4(fa.x, fa.y, fb.x, fb.y);
            }
        } else {
            const float s = sc[j];
            o = make_float4(c_nf4[q[j].x & 15] * s, c_nf4[q[j].y & 15] * s,
                            c_nf4[q[j].z & 15] * s, c_nf4[q[j].w & 15] * s);
        }
        // Streaming store: output never re-read; keep L2 for quant-row dedup.
        __stcs(reinterpret_cast<float4*>(out + (size_t)(tok0 + j) * DIM + d), o);
    }
}

extern "C" void kernel_launch(void* const* d_in, const int* in_sizes, int n_in,
                              void* d_out, int out_size) {
    const void*  ids    = d_in[0];
    const int*   quant  = (const int*)d_in[1];
    const float* scales = (const float*)d_in[2];
    const unsigned short* spec = (const unsigned short*)d_in[3];
    const void*  sidx   = d_in[4];
    float* out = (float*)d_out;

    detect_kernel<<<1, 256>>>((const int*)ids, spec);
    prep_rec_kernel<<<NTOK / 256, 256>>>(ids, sidx);
    tok_embed_kernel<<<NTOK / TPB, 256>>>(quant, scales, spec, out);
}

// round 6
// speedup vs baseline: 1.2197x; 1.0271x over previous
#include <cuda_runtime.h>
#include <cuda_fp16.h>
#include <cuda_bf16.h>

// TokenAwareEmbedding: per-token NF4 dequant + special-token override.
//   0: input_ids          int32|int64 [8, 2048]
//   1: main_quantized     int32       [804112, 64]
//   2: main_scales        fp32        [804112]
//   3: special_embeddings fp32|fp16|bf16 [256, 1024]
//   4: special_indices    int32|int64 [256] (sorted)
// output: fp32 [8, 2048, 1024]

#define VOCAB 50257
#define DIM 1024
#define NTOK (8 * 2048)
#define NSPEC 256
#define TPB 8            // tokens per block in main kernel

__constant__ float c_nf4[16] = {
    -1.0f, -0.6962f, -0.5251f, -0.3949f, -0.2844f, -0.1848f, -0.0911f, 0.0f,
    0.0796f, 0.1609f, 0.2461f, 0.3379f, 0.4407f, 0.5626f, 0.723f, 1.0f};

// packed per-token record: t[0:16) | (row+1)[16:25) | dt[25:27)
__device__ int g_rec[NTOK];

__device__ __forceinline__ float finite_abs(float v) {
    return isfinite(v) ? fabsf(v) : 1e30f;
}

// ── K1: per-token record; detection fused (each block re-detects, L2-cheap) ─
__global__ __launch_bounds__(256)
void prep_rec_kernel(const void* __restrict__ ids,
                     const void* __restrict__ sidx,
                     const unsigned short* __restrict__ specu) {
    __shared__ int   s_sidx[NSPEC];
    __shared__ float s_sum[3][8];
    __shared__ float s_max[3][8];
    __shared__ int   s_info;  // wide | dt<<1
    const int tid = threadIdx.x;

    // -- dtype detection over first 1024 spec values (3 candidate reads) --
    float sum[3] = {0.f, 0.f, 0.f};
    float mx[3] = {0.f, 0.f, 0.f};
    #pragma unroll
    for (int k = 0; k < 4; k++) {
        int i = tid * 4 + k;
        float vh = finite_abs(__half2float(((const __half*)specu)[i]));
        float vb = finite_abs(__bfloat162float(((const __nv_bfloat16*)specu)[i]));
        float vf = finite_abs(((const float*)specu)[i]);
        sum[0] += vh; mx[0] = fmaxf(mx[0], vh);
        sum[1] += vb; mx[1] = fmaxf(mx[1], vb);
        sum[2] += vf; mx[2] = fmaxf(mx[2], vf);
    }
    #pragma unroll
    for (int c = 0; c < 3; c++) {
        #pragma unroll
        for (int o = 16; o > 0; o >>= 1) {
            sum[c] += __shfl_down_sync(0xFFFFFFFFu, sum[c], o);
            mx[c] = fmaxf(mx[c], __shfl_down_sync(0xFFFFFFFFu, mx[c], o));
        }
        if ((tid & 31) == 0) { s_sum[c][tid >> 5] = sum[c]; s_max[c][tid >> 5] = mx[c]; }
    }
    __syncthreads();
    if (tid == 0) {
        float S[3], M[3];
        #pragma unroll
        for (int c = 0; c < 3; c++) {
            S[c] = 0.f; M[c] = 0.f;
            #pragma unroll
            for (int w = 0; w < 8; w++) { S[c] += s_sum[c][w]; M[c] = fmaxf(M[c], s_max[c][w]); }
            S[c] *= (1.0f / 1024.0f);  // mean |x|; N(0,1) -> ~0.798
        }
        int dt;
        if (M[0] < 10.f && fabsf(S[0] - 0.8f) < 0.3f)      dt = 1;  // fp16
        else if (M[1] < 10.f && fabsf(S[1] - 0.8f) < 0.3f) dt = 2;  // bf16
        else                                                dt = 0;  // fp32

        // index width: int64 values < 2^31 have zero odd int32 words
        const int* w32 = (const int*)ids;
        bool wide = true;
        #pragma unroll
        for (int k = 1; k < 64; k += 2) wide &= (w32[k] == 0);
        s_info = (wide ? 1 : 0) | (dt << 1);
    }
    __syncthreads();
    const bool wide = (s_info & 1) != 0;
    const int  dt   = s_info >> 1;

    // -- load special indices to shared --
    s_sidx[tid] = wide ? (int)((const long long*)sidx)[tid]
                       : ((const int*)sidx)[tid];
    __syncthreads();

    const int tok = blockIdx.x * 256 + tid;
    long long tl = wide ? ((const long long*)ids)[tok]
                        : (long long)((const int*)ids)[tok];
    if (tl < 0) tl = 0;
    if (tl >= VOCAB) tl = VOCAB - 1;
    const int t = (int)tl;

    // upper_bound; last-wins for duplicate sorted indices (XLA scatter)
    int lo = 0, hi = NSPEC;
    #pragma unroll
    for (int it = 0; it < 8; it++) {
        int mid = (lo + hi) >> 1;
        if (s_sidx[mid] <= t) lo = mid + 1; else hi = mid;
    }
    const int r = (lo > 0 && s_sidx[lo - 1] == t) ? (lo - 1) : -1;
    g_rec[tok] = t | ((r + 1) << 16) | (dt << 25);
}

// ── K2: main gather/dequant, 8 tokens per block (front-batched loads) ───────
__global__ __launch_bounds__(256)
void tok_embed_kernel(const int* __restrict__ quant,
                      const float* __restrict__ scales,
                      const unsigned short* __restrict__ specu,
                      float* __restrict__ out) {
    const int tok0 = blockIdx.x * TPB;
    const int4 ra = *reinterpret_cast<const int4*>(g_rec + tok0);      // broadcast
    const int4 rb = *reinterpret_cast<const int4*>(g_rec + tok0 + 4);
    const int rec[TPB] = {ra.x, ra.y, ra.z, ra.w, rb.x, rb.y, rb.z, rb.w};
    const int d = threadIdx.x * 4;  // 4 consecutive dims per thread

    // Phase 1: front-batch all independent quant loads (MLP = 8/thread)
    int4 q[TPB];
    float sc[TPB];
    #pragma unroll
    for (int j = 0; j < TPB; j++) {
        const int t = rec[j] & 0xFFFF;
        const int r = ((rec[j] >> 16) & 0x1FF) - 1;
        if (r < 0) {
            q[j] = *reinterpret_cast<const int4*>(quant + (size_t)t * DIM + d);
            sc[j] = __ldg(scales + t * (DIM / 64) + (d >> 6));
        }
    }

    // Phase 2: compute + streaming stores
    #pragma unroll
    for (int j = 0; j < TPB; j++) {
        const int r = ((rec[j] >> 16) & 0x1FF) - 1;
        float4 o;
        if (r >= 0) {
            const int dt = (rec[j] >> 25) & 3;
            const size_t base = (size_t)r * DIM + d;
            if (dt == 0) {
                o = *reinterpret_cast<const float4*>((const float*)specu + base);
            } else if (dt == 1) {
                const __half2* sp = reinterpret_cast<const __half2*>((const __half*)specu + base);
                float2 fa = __half22float2(sp[0]);
                float2 fb = __half22float2(sp[1]);
                o = make_float4(fa.x, fa.y, fb.x, fb.y);
            } else {
                const __nv_bfloat162* sp =
                    reinterpret_cast<const __nv_bfloat162*>((const __nv_bfloat16*)specu + base);
                float2 fa = __bfloat1622float2(sp[0]);
                float2 fb = __bfloat1622float2(sp[1]);
                o = make_float4(fa.x, fa.y, fb.x, fb.y);
            }
        } else {
            const float s = sc[j];
            o = make_float4(c_nf4[q[j].x & 15] * s, c_nf4[q[j].y & 15] * s,
                            c_nf4[q[j].z & 15] * s, c_nf4[q[j].w & 15] * s);
        }
        // Streaming store: output never re-read; keep L2 for quant-row dedup.
        __stcs(reinterpret_cast<float4*>(out + (size_t)(tok0 + j) * DIM + d), o);
    }
}

extern "C" void kernel_launch(void* const* d_in, const int* in_sizes, int n_in,
                              void* d_out, int out_size) {
    const void*  ids    = d_in[0];
    const int*   quant  = (const int*)d_in[1];
    const float* scales = (const float*)d_in[2];
    const unsigned short* spec = (const unsigned short*)d_in[3];
    const void*  sidx   = d_in[4];
    float* out = (float*)d_out;

    prep_rec_kernel<<<NTOK / 256, 256>>>(ids, sidx, spec);
    tok_embed_kernel<<<NTOK / TPB, 256>>>(quant, scales, spec, out);
}